// round 15
// baseline (speedup 1.0000x reference)
#include <cuda_runtime.h>
#include <cuda_bf16.h>
#include <cuda_fp16.h>
#include <cstdint>

#define NN   50000
#define DEGQ 16
#define EE   (NN*DEGQ)
#define HH   32
#define FIN  128
#define NPB  40      // nodes per block (k1/k2/k3)
#define TPB  5       // edge tiles per block (8 nodes / 128 edges each)

// ---------------- scratch (device globals; no allocation) ----------------
__device__ __half g_Th[(size_t)EE*HH];     // T1 in fp16 : 51.2MB
__device__ float g_u1[NN*HH];
__device__ float g_v1[NN*HH];
__device__ float g_s2[NN*HH];
__device__ float g_u2[NN*HH];
__device__ float g_v2[NN*HH];

// ---------------- mma.sync helpers ----------------
__device__ __forceinline__ uint32_t smem_u32(const void* p) {
    uint32_t a;
    asm("{ .reg .u64 t; cvta.to.shared.u64 t, %1; cvt.u32.u64 %0, t; }" : "=r"(a) : "l"(p));
    return a;
}
__device__ __forceinline__ void ldsm4(uint32_t* r, uint32_t addr) {
    asm volatile("ldmatrix.sync.aligned.m8n8.x4.shared.b16 {%0,%1,%2,%3}, [%4];"
        : "=r"(r[0]), "=r"(r[1]), "=r"(r[2]), "=r"(r[3]) : "r"(addr));
}
__device__ __forceinline__ void ldsm2(uint32_t* r, uint32_t addr) {
    asm volatile("ldmatrix.sync.aligned.m8n8.x2.shared.b16 {%0,%1}, [%2];"
        : "=r"(r[0]), "=r"(r[1]) : "r"(addr));
}
__device__ __forceinline__ void mma_bf16(float* c, const uint32_t* a, const uint32_t* b) {
    asm volatile("mma.sync.aligned.m16n8k16.row.col.f32.bf16.bf16.f32 "
        "{%0,%1,%2,%3}, {%4,%5,%6,%7}, {%8,%9}, {%0,%1,%2,%3};"
        : "+f"(c[0]), "+f"(c[1]), "+f"(c[2]), "+f"(c[3])
        : "r"(a[0]), "r"(a[1]), "r"(a[2]), "r"(a[3]), "r"(b[0]), "r"(b[1]));
}
__device__ __forceinline__ void bf16split(float v, __nv_bfloat16& hi, __nv_bfloat16& lo) {
    hi = __float2bfloat16(v);
    lo = __float2bfloat16(v - __bfloat162float(hi));
}
__device__ __forceinline__ uint32_t cvt2bf(float lo, float hi) {
    uint32_t r;
    asm("cvt.rn.bf16x2.f32 %0, %1, %2;" : "=r"(r) : "f"(hi), "f"(lo));
    return r;
}

// ---- k1 smem layout (bytes). Main pitch 272; tail pitch 80. ----
#define PITCH    272
#define OFF_A1   0
#define OFF_A2   34816
#define OFF_W1   69632                  // we1s (main), then wn1p (tail, restaged)
#define OFF_W2   78336
#define OFF_TA1  87040                  // asum split hi : 40 x 272
#define OFF_TA2  97920                  // asum split lo
#define K1_SMEM  108800                 // 2 CTAs/SM
// tail aliases inside the A region (free after the tile loop):
#define TC1  0                          // B'' = [P;Q;wn2s] hi : 96 x 80
#define TC2  7680
#define TX1  15360                      // x split hi : 48 x 80 (rows 40-47 zero)
#define TX2  19200
#define SXO  (23040/4)                  // sX floats : 40 x 34
#define SXP  34
#define TP   80

// ---- one MMA2 task (k1): rows [rt*16,+16) of x @ B'' section sec ----
__device__ __forceinline__ void mma2_task(int task, uint32_t sb, int blk, int l,
        const float* __restrict__ be1p, const float* __restrict__ be1s,
        const float* __restrict__ bn2p, const float* __restrict__ bn2s) {
    const int rt = task / 3, sec = task - rt*3;
    float c[4][4];
    #pragma unroll
    for (int nt = 0; nt < 4; nt++)
        c[nt][0] = c[nt][1] = c[nt][2] = c[nt][3] = 0.f;
    const uint32_t a_off = (uint32_t)((rt*16 + (l & 15))*TP + (l >> 4)*16);
    const uint32_t b_off = (uint32_t)((sec*32 + (l & 7))*TP + ((l >> 3) & 1)*16);
    #pragma unroll
    for (int ks = 0; ks < 2; ks++) {
        const uint32_t kb = ks*32;
        uint32_t a1[4], a2[4];
        ldsm4(a1, sb + TX1 + a_off + kb);
        ldsm4(a2, sb + TX2 + a_off + kb);
        #pragma unroll
        for (int nt = 0; nt < 4; nt++) {
            uint32_t b1[2], b2[2];
            const uint32_t bo = b_off + (uint32_t)(nt*8*TP) + kb;
            ldsm2(b1, sb + TC1 + bo);
            ldsm2(b2, sb + TC2 + bo);
            mma_bf16(c[nt], a1, b1);
            mma_bf16(c[nt], a1, b2);
            mma_bf16(c[nt], a2, b1);
        }
    }
    const int r0 = l >> 2, c0 = (l & 3)*2;
    #pragma unroll
    for (int nt = 0; nt < 4; nt++) {
        const int h0 = nt*8 + c0;
        #pragma unroll
        for (int half = 0; half < 2; half++) {
            const int row = rt*16 + r0 + half*8;
            if (row < NPB) {
                const int node = blk*NPB + row;
                float2 r = make_float2(c[nt][half*2], c[nt][half*2+1]);
                if (sec == 0) {
                    r.x += __ldg(be1p+h0)   + __ldg(be1s+h0);
                    r.y += __ldg(be1p+h0+1) + __ldg(be1s+h0+1);
                    *(float2*)&g_u1[node*HH + h0] = r;
                } else if (sec == 1) {
                    *(float2*)&g_v1[node*HH + h0] = r;
                } else {
                    r.x += __ldg(bn2p+h0)   + __ldg(bn2s+h0);
                    r.y += __ldg(bn2p+h0+1) + __ldg(bn2s+h0+1);
                    *(float2*)&g_s2[node*HH + h0] = r;
                }
            }
        }
    }
}

// ============================================================================
// K1 (unchanged from round 14): 40 nodes / 640 edges per block.
// ============================================================================
__global__ __launch_bounds__(256, 2) void k1(const float* __restrict__ X,
                                             const int*   __restrict__ dst,
                                             const float* __restrict__ D,
                                             const float* __restrict__ we1s,
                                             const float* __restrict__ wn1p,
                                             const float* __restrict__ bn1p,
                                             const float* __restrict__ bn1s,
                                             const float* __restrict__ we1p,
                                             const float* __restrict__ be1p,
                                             const float* __restrict__ be1s,
                                             const float* __restrict__ wn2s,
                                             const float* __restrict__ bn2p,
                                             const float* __restrict__ bn2s) {
    extern __shared__ unsigned char smb[];
    float* sf = (float*)smb;
    const uint32_t sb = smem_u32(smb);

    const int tid = threadIdx.x;
    const int blk = blockIdx.x;
    const int w = tid >> 5, l = tid & 31;

    #pragma unroll
    for (int r = 0; r < 16; r++) {
        int idx = tid + 256*r;
        int h = idx >> 7, k = idx & 127;
        __nv_bfloat16 w1, w2;
        bf16split(__ldg(we1s + idx), w1, w2);
        uint32_t o = h*PITCH + 2*k;
        *(__nv_bfloat16*)(smb + OFF_W1 + o) = w1;
        *(__nv_bfloat16*)(smb + OFF_W2 + o) = w2;
    }

    float wreg[32];
    float breg[24];

    #pragma unroll 1
    for (int t = 0; t < TPB; t++) {
        const int node = blk*NPB + t*8 + w;
        const float4 xv = ((const float4*)(X + (size_t)node*FIN))[l];
        float4 asum = make_float4(0.f, 0.f, 0.f, 0.f);
        const int* de = dst + node*DEGQ;
        #pragma unroll
        for (int j = 0; j < DEGQ; j++) {
            int d = __ldg(de + j);
            float4 g = ((const float4*)(X + (size_t)d*FIN))[l];
            float4 a;
            a.x = fabsf(xv.x - g.x);
            a.y = fabsf(xv.y - g.y);
            a.z = fabsf(xv.z - g.z);
            a.w = fabsf(xv.w - g.w);
            asum.x += a.x; asum.y += a.y; asum.z += a.z; asum.w += a.w;

            uint32_t p01 = cvt2bf(a.x, a.y);
            uint32_t p23 = cvt2bf(a.z, a.w);
            float hx = __uint_as_float(p01 << 16);
            float hy = __uint_as_float(p01 & 0xFFFF0000u);
            float hz = __uint_as_float(p23 << 16);
            float hw = __uint_as_float(p23 & 0xFFFF0000u);
            uint32_t q01 = cvt2bf(a.x - hx, a.y - hy);
            uint32_t q23 = cvt2bf(a.z - hz, a.w - hw);
            uint64_t hiw = (uint64_t)p01 | ((uint64_t)p23 << 32);
            uint64_t low = (uint64_t)q01 | ((uint64_t)q23 << 32);

            const int row = w*DEGQ + j;
            uint32_t o = row*PITCH + l*8;
            *(uint64_t*)(smb + OFF_A1 + o) = hiw;
            *(uint64_t*)(smb + OFF_A2 + o) = low;
        }
        {
            uint32_t p01 = cvt2bf(asum.x, asum.y);
            uint32_t p23 = cvt2bf(asum.z, asum.w);
            float hx = __uint_as_float(p01 << 16);
            float hy = __uint_as_float(p01 & 0xFFFF0000u);
            float hz = __uint_as_float(p23 << 16);
            float hw = __uint_as_float(p23 & 0xFFFF0000u);
            uint32_t q01 = cvt2bf(asum.x - hx, asum.y - hy);
            uint32_t q23 = cvt2bf(asum.z - hz, asum.w - hw);
            uint64_t hiw = (uint64_t)p01 | ((uint64_t)p23 << 32);
            uint64_t low = (uint64_t)q01 | ((uint64_t)q23 << 32);
            const int tr = t*8 + w;
            *(uint64_t*)(smb + OFF_TA1 + tr*PITCH + l*8) = hiw;
            *(uint64_t*)(smb + OFF_TA2 + tr*PITCH + l*8) = low;
        }
        __syncthreads();

        if (w < 4) {
            const int wr = w*32;
            float c[2][4][4];
            #pragma unroll
            for (int tt = 0; tt < 2; tt++)
                #pragma unroll
                for (int nt = 0; nt < 4; nt++)
                    c[tt][nt][0] = c[tt][nt][1] = c[tt][nt][2] = c[tt][nt][3] = 0.f;

            const uint32_t a_off = (uint32_t)((wr + (l & 15))*PITCH + (l >> 4)*16);
            const uint32_t b_off = (uint32_t)(((l & 7))*PITCH + ((l >> 3) & 1)*16);

            #pragma unroll
            for (int ks = 0; ks < 8; ks++) {
                const uint32_t kb = ks*32;
                uint32_t bfr[4][2][2];
                #pragma unroll
                for (int nt = 0; nt < 4; nt++) {
                    const uint32_t bo = b_off + (uint32_t)(nt*8*PITCH) + kb;
                    ldsm2(bfr[nt][0], sb + OFF_W1 + bo);
                    ldsm2(bfr[nt][1], sb + OFF_W2 + bo);
                }
                #pragma unroll
                for (int tt = 0; tt < 2; tt++) {
                    uint32_t a1[4], a2[4];
                    ldsm4(a1, sb + OFF_A1 + a_off + (uint32_t)(tt*16*PITCH) + kb);
                    ldsm4(a2, sb + OFF_A2 + a_off + (uint32_t)(tt*16*PITCH) + kb);
                    #pragma unroll
                    for (int nt = 0; nt < 4; nt++) {
                        mma_bf16(c[tt][nt], a1, bfr[nt][0]);
                        mma_bf16(c[tt][nt], a1, bfr[nt][1]);
                        mma_bf16(c[tt][nt], a2, bfr[nt][0]);
                    }
                }
            }

            const int r0 = l >> 2, c0 = (l & 3)*2;
            #pragma unroll
            for (int tt = 0; tt < 2; tt++) {
                const size_t base = (size_t)blk*(NPB*DEGQ) + t*128 + wr + tt*16;
                #pragma unroll
                for (int nt = 0; nt < 4; nt++) {
                    __half2 h01 = __floats2half2_rn(c[tt][nt][0], c[tt][nt][1]);
                    __half2 h23 = __floats2half2_rn(c[tt][nt][2], c[tt][nt][3]);
                    *(__half2*)&g_Th[(base + r0)*HH + nt*8 + c0]     = h01;
                    *(__half2*)&g_Th[(base + r0 + 8)*HH + nt*8 + c0] = h23;
                }
            }
        } else if (t == 0) {
            const int ltid = tid - 128;
            #pragma unroll
            for (int r = 0; r < 32; r++)
                wreg[r] = __ldg(wn1p + ltid + 128*r);
            const int cgrp = ltid >> 5, kk = ltid & 31;
            #pragma unroll
            for (int r = 0; r < 8; r++) {
                int n = 4*r + cgrp;
                float wa = __ldg(we1p + n*64 + kk), wb = __ldg(we1p + n*64 + 32 + kk);
                breg[r] = 0.5f*(wa + wb);
            }
            #pragma unroll
            for (int r = 8; r < 16; r++) {
                int h = 4*(r-8) + cgrp;
                float wa = __ldg(we1p + h*64 + kk), wb = __ldg(we1p + h*64 + 32 + kk);
                breg[r] = 0.5f*(wb - wa);
            }
            #pragma unroll
            for (int r = 16; r < 24; r++) {
                int h = 4*(r-16) + cgrp;
                breg[r] = __ldg(wn2s + h*32 + kk);
            }
        }
        __syncthreads();
    }

    if (w >= 4) {
        const int ltid = tid - 128;
        #pragma unroll
        for (int r = 0; r < 32; r++) {
            __nv_bfloat16 w1, w2;
            bf16split(wreg[r], w1, w2);
            uint32_t o = r*PITCH + 2*ltid;
            *(__nv_bfloat16*)(smb + OFF_W1 + o) = w1;
            *(__nv_bfloat16*)(smb + OFF_W2 + o) = w2;
        }
        const int cgrp = ltid >> 5, kk = ltid & 31;
        #pragma unroll
        for (int r = 0; r < 24; r++) {
            int n = 4*r + cgrp;
            __nv_bfloat16 b1, b2;
            bf16split(breg[r], b1, b2);
            uint32_t o = n*TP + 2*kk;
            *(__nv_bfloat16*)(smb + TC1 + o) = b1;
            *(__nv_bfloat16*)(smb + TC2 + o) = b2;
        }
    } else {
        #pragma unroll
        for (int r = 0; r < 2; r++) {
            int idx2 = tid + 128*r;
            if (idx2 < 160) {
                *(uint32_t*)(smb + TX1 + NPB*TP + idx2*4) = 0u;
                *(uint32_t*)(smb + TX2 + NPB*TP + idx2*4) = 0u;
            }
        }
    }
    __syncthreads();

    if (w < 3) {
        const int rowbase = (w == 2) ? 24 : w*16;
        float c[4][4];
        #pragma unroll
        for (int nt = 0; nt < 4; nt++)
            c[nt][0] = c[nt][1] = c[nt][2] = c[nt][3] = 0.f;
        const uint32_t a_off = (uint32_t)((rowbase + (l & 15))*PITCH + (l >> 4)*16);
        const uint32_t b_off = (uint32_t)((l & 7)*PITCH + ((l >> 3) & 1)*16);
        #pragma unroll
        for (int ks = 0; ks < 8; ks++) {
            const uint32_t kb = ks*32;
            uint32_t a1[4], a2[4];
            ldsm4(a1, sb + OFF_TA1 + a_off + kb);
            ldsm4(a2, sb + OFF_TA2 + a_off + kb);
            #pragma unroll
            for (int nt = 0; nt < 4; nt++) {
                uint32_t b1[2], b2[2];
                const uint32_t bo = b_off + (uint32_t)(nt*8*PITCH) + kb;
                ldsm2(b1, sb + OFF_W1 + bo);
                ldsm2(b2, sb + OFF_W2 + bo);
                mma_bf16(c[nt], a1, b1);
                mma_bf16(c[nt], a1, b2);
                mma_bf16(c[nt], a2, b1);
            }
        }
        const int r0 = l >> 2, c0 = (l & 3)*2;
        #pragma unroll
        for (int nt = 0; nt < 4; nt++) {
            const int nd0 = rowbase + r0;
            if (w != 2)
                *(float2*)&sf[SXO + nd0*SXP + nt*8 + c0] = make_float2(c[nt][0], c[nt][1]);
            *(float2*)&sf[SXO + (nd0+8)*SXP + nt*8 + c0] = make_float2(c[nt][2], c[nt][3]);
        }
    }
    __syncthreads();

    #pragma unroll
    for (int r = 0; r < 5; r++) {
        int idx = tid + 256*r;
        int nd = idx >> 5, h = idx & 31;
        int node = blk*NPB + nd;
        const float invD = 1.0f / __ldg(D + node);
        float x = fmaxf(fmaf(sf[SXO + nd*SXP + h], invD,
                             __ldg(bn1p+h) + __ldg(bn1s+h)), 0.f);
        __nv_bfloat16 xh, xl;
        bf16split(x, xh, xl);
        *(__nv_bfloat16*)(smb + TX1 + nd*TP + 2*h) = xh;
        *(__nv_bfloat16*)(smb + TX2 + nd*TP + 2*h) = xl;
    }
    __syncthreads();

    mma2_task(w, sb, blk, l, be1p, be1s, bn2p, bn2s);
    if (w == 7)
        mma2_task(8, sb, blk, l, be1p, be1s, bn2p, bn2s);
}

// ============================================================================
// K2' (amortized, tensor tail): 40 nodes/block.
//   gather: Asum1 (fp32) -> bf16 split TA (no syncs; warp-private rows)
//   MMA1 (warps 0-2): s = Asum1 @ wn2p^T ; x = relu(s/D + s2)
//   MMA2 (warps 0-5): u2 = x@P^T (+biases), v2 = x@Q^T
// ============================================================================
#define K2TP 80
__global__ __launch_bounds__(256, 2) void k2(const int* __restrict__ dst,
                                             const float* __restrict__ D,
                                             const float* __restrict__ wn2p,
                                             const float* __restrict__ we2p,
                                             const float* __restrict__ be2p,
                                             const float* __restrict__ be2s) {
    __shared__ __align__(16) unsigned char TA1k[NPB*K2TP];
    __shared__ __align__(16) unsigned char TA2k[NPB*K2TP];
    __shared__ __align__(16) unsigned char B1k[96*K2TP];
    __shared__ __align__(16) unsigned char B2k[96*K2TP];
    __shared__ __align__(16) unsigned char TX1k[48*K2TP];
    __shared__ __align__(16) unsigned char TX2k[48*K2TP];
    __shared__ float sX2[NPB*SXP];

    const int tid = threadIdx.x, blk = blockIdx.x;
    const int w = tid >> 5, l = tid & 31;

    // stage B = [wn2p ; P ; Q] (96 x 32) split
    #pragma unroll
    for (int r = 0; r < 12; r++) {
        int idx = tid + 256*r;                 // 0..3071
        int n = idx >> 5, k = idx & 31;
        float wv;
        if (n < 32) {
            wv = __ldg(wn2p + n*32 + k);
        } else if (n < 64) {
            int h = n - 32;
            float wa = __ldg(we2p + h*64 + k), wb = __ldg(we2p + h*64 + 32 + k);
            wv = 0.5f*(wa + wb);
        } else {
            int h = n - 64;
            float wa = __ldg(we2p + h*64 + k), wb = __ldg(we2p + h*64 + 32 + k);
            wv = 0.5f*(wb - wa);
        }
        __nv_bfloat16 b1, b2;
        bf16split(wv, b1, b2);
        *(__nv_bfloat16*)(B1k + n*K2TP + 2*k) = b1;
        *(__nv_bfloat16*)(B2k + n*K2TP + 2*k) = b2;
    }

    // gather: Asum1 per node (warp = node), 5 tiles, no syncs needed
    #pragma unroll 1
    for (int t = 0; t < TPB; t++) {
        const int node = blk*NPB + t*8 + w;
        const float u1h = g_u1[node*HH + l];
        const int* de = dst + node*DEGQ;
        const size_t ebase = (size_t)node*DEGQ;
        float asum = 0.f;
        #pragma unroll
        for (int j = 0; j < DEGQ; j++) {
            int d = __ldg(de + j);
            float val = u1h + g_v1[d*HH + l] + __half2float(g_Th[(ebase + j)*HH + l]);
            asum += fmaxf(val, 0.f);
        }
        __nv_bfloat16 hi, lo;
        bf16split(asum, hi, lo);
        const int row = t*8 + w;
        *(__nv_bfloat16*)(TA1k + row*K2TP + 2*l) = hi;
        *(__nv_bfloat16*)(TA2k + row*K2TP + 2*l) = lo;
    }
    // zero TX pad rows 40-47 (640 B per buffer = 160 words)
    if (tid < 160) {
        ((uint32_t*)(TX1k + NPB*K2TP))[tid] = 0u;
        ((uint32_t*)(TX2k + NPB*K2TP))[tid] = 0u;
    }
    __syncthreads();

    // MMA1 (warps 0-2): s = Asum1(40x32) @ wn2p^T (B rows 0-31)
    if (w < 3) {
        const int rowbase = (w == 2) ? 24 : w*16;
        float c[4][4];
        #pragma unroll
        for (int nt = 0; nt < 4; nt++)
            c[nt][0] = c[nt][1] = c[nt][2] = c[nt][3] = 0.f;
        const uint32_t a1b = smem_u32(TA1k) + (uint32_t)((rowbase + (l & 15))*K2TP + (l >> 4)*16);
        const uint32_t a2b = smem_u32(TA2k) + (uint32_t)((rowbase + (l & 15))*K2TP + (l >> 4)*16);
        const uint32_t b1b = smem_u32(B1k) + (uint32_t)(((l & 7))*K2TP + ((l >> 3) & 1)*16);
        const uint32_t b2b = smem_u32(B2k) + (uint32_t)(((l & 7))*K2TP + ((l >> 3) & 1)*16);
        #pragma unroll
        for (int ks = 0; ks < 2; ks++) {
            const uint32_t kb = ks*32;
            uint32_t a1[4], a2[4];
            ldsm4(a1, a1b + kb);
            ldsm4(a2, a2b + kb);
            #pragma unroll
            for (int nt = 0; nt < 4; nt++) {
                uint32_t b1[2], b2[2];
                const uint32_t bo = (uint32_t)(nt*8*K2TP) + kb;
                ldsm2(b1, b1b + bo);
                ldsm2(b2, b2b + bo);
                mma_bf16(c[nt], a1, b1);
                mma_bf16(c[nt], a1, b2);
                mma_bf16(c[nt], a2, b1);
            }
        }
        const int r0 = l >> 2, c0 = (l & 3)*2;
        #pragma unroll
        for (int nt = 0; nt < 4; nt++) {
            const int nd0 = rowbase + r0;
            if (w != 2)
                *(float2*)&sX2[nd0*SXP + nt*8 + c0] = make_float2(c[nt][0], c[nt][1]);
            *(float2*)&sX2[(nd0+8)*SXP + nt*8 + c0] = make_float2(c[nt][2], c[nt][3]);
        }
    }
    __syncthreads();

    // x = relu(s/D + s2) -> TX split
    #pragma unroll
    for (int r = 0; r < 5; r++) {
        int idx = tid + 256*r;
        int nd = idx >> 5, h = idx & 31;
        int node = blk*NPB + nd;
        const float invD = 1.0f / __ldg(D + node);
        float x = fmaxf(fmaf(sX2[nd*SXP + h], invD, g_s2[node*HH + h]), 0.f);
        __nv_bfloat16 xh, xl;
        bf16split(x, xh, xl);
        *(__nv_bfloat16*)(TX1k + nd*K2TP + 2*h) = xh;
        *(__nv_bfloat16*)(TX2k + nd*K2TP + 2*h) = xl;
    }
    __syncthreads();

    // MMA2 (warps 0-5): task = w; rt = w>>1 (row tile), sec = w&1 (0=P->u2, 1=Q->v2)
    if (w < 6) {
        const int rt = w >> 1, sec = w & 1;
        float c[4][4];
        #pragma unroll
        for (int nt = 0; nt < 4; nt++)
            c[nt][0] = c[nt][1] = c[nt][2] = c[nt][3] = 0.f;
        const uint32_t a1b = smem_u32(TX1k) + (uint32_t)((rt*16 + (l & 15))*K2TP + (l >> 4)*16);
        const uint32_t a2b = smem_u32(TX2k) + (uint32_t)((rt*16 + (l & 15))*K2TP + (l >> 4)*16);
        const uint32_t boff = (uint32_t)((32 + sec*32 + (l & 7))*K2TP + ((l >> 3) & 1)*16);
        #pragma unroll
        for (int ks = 0; ks < 2; ks++) {
            const uint32_t kb = ks*32;
            uint32_t a1[4], a2[4];
            ldsm4(a1, a1b + kb);
            ldsm4(a2, a2b + kb);
            #pragma unroll
            for (int nt = 0; nt < 4; nt++) {
                uint32_t b1[2], b2[2];
                const uint32_t bo = boff + (uint32_t)(nt*8*K2TP) + kb;
                ldsm2(b1, smem_u32(B1k) + bo);
                ldsm2(b2, smem_u32(B2k) + bo);
                mma_bf16(c[nt], a1, b1);
                mma_bf16(c[nt], a1, b2);
                mma_bf16(c[nt], a2, b1);
            }
        }
        const int r0 = l >> 2, c0 = (l & 3)*2;
        #pragma unroll
        for (int nt = 0; nt < 4; nt++) {
            const int h0 = nt*8 + c0;
            #pragma unroll
            for (int half = 0; half < 2; half++) {
                const int row = rt*16 + r0 + half*8;
                if (row < NPB) {
                    const int node = blk*NPB + row;
                    float2 r = make_float2(c[nt][half*2], c[nt][half*2+1]);
                    if (sec == 0) {
                        r.x += __ldg(be2p+h0)   + __ldg(be2s+h0);
                        r.y += __ldg(be2p+h0+1) + __ldg(be2s+h0+1);
                        *(float2*)&g_u2[node*HH + h0] = r;
                    } else {
                        *(float2*)&g_v2[node*HH + h0] = r;
                    }
                }
            }
        }
    }
}

// ============================================================================
// K3' (amortized): 40 nodes/block, 5 tiles. we2s staged once.
//   per tile: vals1 recompute -> T2 MMA in regs -> fused classifier -> out
// ============================================================================
#define K2P 80
__global__ __launch_bounds__(256) void k3(const int* __restrict__ dst,
                                          const float* __restrict__ we2s,
                                          const float* __restrict__ wc,
                                          const float* __restrict__ bc,
                                          float* __restrict__ out) {
    __shared__ __align__(16) unsigned char sA1[128*K2P];
    __shared__ __align__(16) unsigned char sA2[128*K2P];
    __shared__ __align__(16) unsigned char sB1[32*K2P];
    __shared__ __align__(16) unsigned char sB2[32*K2P];

    const int tid = threadIdx.x, blk = blockIdx.x;
    const int w = tid >> 5, l = tid & 31;

    #pragma unroll
    for (int r = 0; r < 4; r++) {
        int idx = tid + 256*r;
        int n = idx >> 5, k = idx & 31;
        __nv_bfloat16 b1, b2;
        bf16split(__ldg(we2s + idx), b1, b2);
        uint32_t o = n*K2P + 2*k;
        *(__nv_bfloat16*)(sB1 + o) = b1;
        *(__nv_bfloat16*)(sB2 + o) = b2;
    }

    #pragma unroll 1
    for (int t = 0; t < TPB; t++) {
        const int node = blk*NPB + t*8 + w;
        const float u1h = g_u1[node*HH + l];
        const int* de = dst + node*DEGQ;
        const size_t ebase = (size_t)node*DEGQ;
        #pragma unroll
        for (int j = 0; j < DEGQ; j++) {
            int d = __ldg(de + j);
            float val = u1h + g_v1[d*HH + l] + __half2float(g_Th[(ebase + j)*HH + l]);
            val = fmaxf(val, 0.f);
            __nv_bfloat16 b1, b2;
            bf16split(val, b1, b2);
            uint32_t m1 = (uint32_t)__bfloat16_as_ushort(b1);
            uint32_t m2 = (uint32_t)__bfloat16_as_ushort(b2);
            uint32_t o1 = __shfl_down_sync(0xffffffffu, m1, 1);
            uint32_t o2 = __shfl_down_sync(0xffffffffu, m2, 1);
            if (!(l & 1)) {
                const int row = w*DEGQ + j;
                *(uint32_t*)(sA1 + row*K2P + l*2) = m1 | (o1 << 16);
                *(uint32_t*)(sA2 + row*K2P + l*2) = m2 | (o2 << 16);
            }
        }
        __syncthreads();

        float c[4][4];
        #pragma unroll
        for (int nt = 0; nt < 4; nt++)
            c[nt][0] = c[nt][1] = c[nt][2] = c[nt][3] = 0.f;
        {
            const uint32_t a1_base = smem_u32(sA1) + (uint32_t)((w*16 + (l & 15))*K2P + (l >> 4)*16);
            const uint32_t a2_base = smem_u32(sA2) + (uint32_t)((w*16 + (l & 15))*K2P + (l >> 4)*16);
            const uint32_t b1_base = smem_u32(sB1) + (uint32_t)(((l & 7))*K2P + ((l >> 3) & 1)*16);
            const uint32_t b2_base = smem_u32(sB2) + (uint32_t)(((l & 7))*K2P + ((l >> 3) & 1)*16);

            #pragma unroll
            for (int ks = 0; ks < 2; ks++) {
                const uint32_t kb = ks*32;
                uint32_t a1[4], a2[4];
                ldsm4(a1, a1_base + kb);
                ldsm4(a2, a2_base + kb);
                #pragma unroll
                for (int nt = 0; nt < 4; nt++) {
                    uint32_t b1[2], b2[2];
                    ldsm2(b1, b1_base + nt*8*K2P + kb);
                    ldsm2(b2, b2_base + nt*8*K2P + kb);
                    mma_bf16(c[nt], a1, b1);
                    mma_bf16(c[nt], a1, b2);
                    mma_bf16(c[nt], a2, b1);
                }
            }
        }

        const int lg = l & 3, r0 = l >> 2;
        const size_t e0 = (size_t)blk*(NPB*DEGQ) + t*128 + w*16 + r0;
        const size_t e1 = e0 + 8;
        const int d0 = __ldg(dst + e0);
        const int d1 = __ldg(dst + e1);
        float acc0 = 0.f, acc1 = 0.f;
        #pragma unroll
        for (int nt = 0; nt < 4; nt++) {
            const int h0 = nt*8 + lg*2;
            const float2 wcv = *(const float2*)&wc[h0];
            const float2 uu  = *(const float2*)&g_u2[node*HH + h0];
            const float2 va  = *(const float2*)&g_v2[d0*HH + h0];
            const float2 vb  = *(const float2*)&g_v2[d1*HH + h0];
            acc0 += fmaxf(uu.x + va.x + c[nt][0], 0.f) * wcv.x
                  + fmaxf(uu.y + va.y + c[nt][1], 0.f) * wcv.y;
            acc1 += fmaxf(uu.x + vb.x + c[nt][2], 0.f) * wcv.x
                  + fmaxf(uu.y + vb.y + c[nt][3], 0.f) * wcv.y;
        }
        acc0 += __shfl_xor_sync(0xffffffffu, acc0, 1);
        acc0 += __shfl_xor_sync(0xffffffffu, acc0, 2);
        acc1 += __shfl_xor_sync(0xffffffffu, acc1, 1);
        acc1 += __shfl_xor_sync(0xffffffffu, acc1, 2);
        if (lg == 0) {
            const float bcv = __ldg(bc);
            out[e0] = 1.f / (1.f + __expf(-(acc0 + bcv)));
            out[e1] = 1.f / (1.f + __expf(-(acc1 + bcv)));
        }
        __syncthreads();
    }
}

// ============================================================================
extern "C" void kernel_launch(void* const* d_in, const int* in_sizes, int n_in,
                              void* d_out, int out_size) {
    const float* X    = (const float*)d_in[0];
    const int*   dst  = (const int*)  d_in[2];
    const float* D    = (const float*)d_in[3];
    const float* wn1p = (const float*)d_in[4];
    const float* bn1p = (const float*)d_in[5];
    const float* bn1s = (const float*)d_in[7];
    const float* we1p = (const float*)d_in[8];
    const float* be1p = (const float*)d_in[9];
    const float* we1s = (const float*)d_in[10];
    const float* be1s = (const float*)d_in[11];
    const float* wn2p = (const float*)d_in[12];
    const float* bn2p = (const float*)d_in[13];
    const float* wn2s = (const float*)d_in[14];
    const float* bn2s = (const float*)d_in[15];
    const float* we2p = (const float*)d_in[16];
    const float* be2p = (const float*)d_in[17];
    const float* we2s = (const float*)d_in[18];
    const float* be2s = (const float*)d_in[19];
    const float* wc   = (const float*)d_in[20];
    const float* bc   = (const float*)d_in[21];
    float* out = (float*)d_out;

    cudaFuncSetAttribute(k1, cudaFuncAttributeMaxDynamicSharedMemorySize, K1_SMEM);

    k1 <<<NN/NPB, 256, K1_SMEM>>>(X, dst, D, we1s, wn1p, bn1p, bn1s,
                                  we1p, be1p, be1s, wn2s, bn2p, bn2s);
    k2 <<<NN/NPB, 256>>>(dst, D, wn2p, we2p, be2p, be2s);
    k3 <<<NN/NPB, 256>>>(dst, we2s, wc, bc, out);
}